// round 11
// baseline (speedup 1.0000x reference)
#include <cuda_runtime.h>
#include <cuda_bf16.h>
#include <math.h>
#include <stdint.h>

#define B 128
#define DIN 512
#define E 256
#define H 512
#define V 32000
#define L 16
#define TH3 1536

#define LOG2E_F 1.4426950408889634f
#define CSHIFT 10.0f

typedef unsigned int u32;
typedef unsigned long long u64;

// ---------------- scratch (static device globals; no allocation) ----------------
__device__ float g_h[B * H];
__device__ float g_e[B * E];
__device__ float g_gx[B * TH3];
__device__ float g_gh[B * TH3];
__device__ float g_z[B * V];
__device__ float g_red[B * 4];            // per-row {S1, T1, S2, pad} plain sums

__device__ __nv_bfloat16 g_WoutH[V * H],  g_WoutL[V * H];
__device__ __nv_bfloat16 g_WembH[E * V],  g_WembL[E * V];
__device__ __nv_bfloat16 g_WihH[TH3 * E], g_WihL[TH3 * E];
__device__ __nv_bfloat16 g_WhhH[TH3 * H], g_WhhL[TH3 * H];
__device__ __nv_bfloat16 g_WagH[H * DIN], g_WagL[H * DIN];
__device__ __nv_bfloat16 g_xH[B * DIN],   g_xL[B * DIN];
__device__ __nv_bfloat16 g_hH[B * H],     g_hL[B * H];

#define SEQ_BSTRIDE ((size_t)(L + 1) * V)
#define LOG_OFF ((size_t)B * (L + 1) * V)
#define ENT_OFF (LOG_OFF + (size_t)B * L * V)

// ---------------- PTX helpers ----------------
__device__ __forceinline__ u32 smem_u32(const void* p) {
    u32 a;
    asm("{ .reg .u64 t; cvta.to.shared.u64 t, %1; cvt.u32.u64 %0, t; }" : "=r"(a) : "l"(p));
    return a;
}
__device__ __forceinline__ void cp16(u32 saddr, const void* g) {
    asm volatile("cp.async.cg.shared.global [%0], [%1], 16;" :: "r"(saddr), "l"(g));
}
__device__ __forceinline__ void ldsm4(u32 addr, u32& r0, u32& r1, u32& r2, u32& r3) {
    asm volatile("ldmatrix.sync.aligned.m8n8.x4.shared.b16 {%0,%1,%2,%3}, [%4];"
        : "=r"(r0), "=r"(r1), "=r"(r2), "=r"(r3) : "r"(addr));
}
__device__ __forceinline__ void mma16816(float* c, const u32* a, u32 b0, u32 b1) {
    asm volatile(
        "mma.sync.aligned.m16n8k16.row.col.f32.bf16.bf16.f32 "
        "{%0,%1,%2,%3},{%4,%5,%6,%7},{%8,%9},{%0,%1,%2,%3};"
        : "+f"(c[0]), "+f"(c[1]), "+f"(c[2]), "+f"(c[3])
        : "r"(a[0]), "r"(a[1]), "r"(a[2]), "r"(a[3]), "r"(b0), "r"(b1));
}

#define BM 128
#define BN 128
#define BK 32
#define STAGES 3
#define TILE_BYTES (BM * BK * 2)
#define STAGE_BYTES (4 * TILE_BYTES)
#define GEMM_SMEM (STAGES * STAGE_BYTES)  // 98304

// fp32-A variant smem layout
#define A32_ROWB 144                       // 36 floats per row (padded)
#define A32_BYTES (BM * A32_ROWB)          // 18432
#define STG32 (A32_BYTES + 2 * TILE_BYTES) // 34816
#define SMEM32 (STAGES * STG32)            // 104448

__device__ __forceinline__ u32 swz(int row, int seg) {
    return (u32)(row * 64 + ((seg ^ ((row >> 1) & 3)) << 4));
}

// ---------------- bf16-split HMMA GEMM core (bf16 A operands) ----------------
// MODE 2: store + bf16 split out. MODE 3: store + atomic softmax sums (logits).
template <int MODE>
__device__ __forceinline__ void gemm_core(
    const __nv_bfloat16* __restrict__ Ah, const __nv_bfloat16* __restrict__ Al, int lda,
    const __nv_bfloat16* __restrict__ Bh, const __nv_bfloat16* __restrict__ Bl, int ldb,
    const float* __restrict__ bias,
    float* __restrict__ C, int ldc,
    __nv_bfloat16* __restrict__ Ch, __nv_bfloat16* __restrict__ Cl,
    int kPerSplit, int bx, int by, char* smem,
    const float* __restrict__ gum, int step)
{
    const u32 sb = smem_u32(smem);
    const int t = threadIdx.x;
    const int lane = t & 31, wid = t >> 5;
    const int warpM = wid & 3, warpN = wid >> 2;
    const int n0 = bx * BN;
    const int kb0 = by * kPerSplit;
    const int iters = kPerSplit / BK;

    float acc[2][8][4];
#pragma unroll
    for (int i = 0; i < 2; i++)
#pragma unroll
        for (int j = 0; j < 8; j++)
#pragma unroll
            for (int k = 0; k < 4; k++) acc[i][j][k] = 0.f;

    auto load_stage = [&](int j) {
        const int stg = j % STAGES;
        const int k0 = kb0 + j * BK;
        const u32 sbase = sb + stg * STAGE_BYTES;
#pragma unroll
        for (int tile = 0; tile < 4; tile++) {
            const __nv_bfloat16* src = (tile == 0) ? Ah : (tile == 1) ? Al : (tile == 2) ? Bh : Bl;
            const int ld = (tile < 2) ? lda : ldb;
            const int r0 = (tile < 2) ? 0 : n0;
#pragma unroll
            for (int i = 0; i < 2; i++) {
                int c = t + i * 256;
                int row = c >> 2, seg = c & 3;
                const void* g = src + (size_t)(r0 + row) * ld + k0 + seg * 8;
                cp16(sbase + tile * TILE_BYTES + swz(row, seg), g);
            }
        }
        asm volatile("cp.async.commit_group;" ::: "memory");
    };

    auto compute = [&](int stg) {
        const u32 sbase = sb + stg * STAGE_BYTES;
#pragma unroll
        for (int ks = 0; ks < 2; ks++) {
            u32 aH[2][4], aL[2][4];
#pragma unroll
            for (int mt = 0; mt < 2; mt++) {
                int row = warpM * 32 + mt * 16 + (lane & 15);
                int ch = ks * 2 + (lane >> 4);
                u32 ad = sbase + swz(row, ch);
                ldsm4(ad, aH[mt][0], aH[mt][1], aH[mt][2], aH[mt][3]);
                ldsm4(ad + TILE_BYTES, aL[mt][0], aL[mt][1], aL[mt][2], aL[mt][3]);
            }
#pragma unroll
            for (int ntp = 0; ntp < 4; ntp++) {
                int nr = warpN * 64 + ntp * 16 + ((lane >> 4) << 3) + (lane & 7);
                int ch = ks * 2 + ((lane >> 3) & 1);
                u32 bd = sbase + 2 * TILE_BYTES + swz(nr, ch);
                u32 bh[4], bl[4];
                ldsm4(bd, bh[0], bh[1], bh[2], bh[3]);
                ldsm4(bd + TILE_BYTES, bl[0], bl[1], bl[2], bl[3]);
#pragma unroll
                for (int mt = 0; mt < 2; mt++) {
                    mma16816(acc[mt][2 * ntp],     aH[mt], bh[0], bh[1]);
                    mma16816(acc[mt][2 * ntp],     aL[mt], bh[0], bh[1]);
                    mma16816(acc[mt][2 * ntp],     aH[mt], bl[0], bl[1]);
                    mma16816(acc[mt][2 * ntp + 1], aH[mt], bh[2], bh[3]);
                    mma16816(acc[mt][2 * ntp + 1], aL[mt], bh[2], bh[3]);
                    mma16816(acc[mt][2 * ntp + 1], aH[mt], bl[2], bl[3]);
                }
            }
        }
    };

    load_stage(0);
    load_stage(1);

    for (int it = 0; it < iters; it++) {
        if (it == iters - 1) asm volatile("cp.async.wait_group 0;" ::: "memory");
        else                 asm volatile("cp.async.wait_group 1;" ::: "memory");
        __syncthreads();
        int jn = it + STAGES - 1;
        if (jn < iters) load_stage(jn);
        compute(it % STAGES);
    }

    const int gq = lane >> 2, cpair = lane & 3;

    if (MODE == 3) {
        // store z + per-row plain exp-sums, atomically accumulated into g_red
        __syncthreads();
        float* sp = reinterpret_cast<float*>(smem);      // [128][2][3]
#pragma unroll
        for (int mt = 0; mt < 2; mt++)
#pragma unroll
            for (int hh = 0; hh < 2; hh++) {
                const int row = warpM * 32 + mt * 16 + hh * 8 + gq;
                float s1 = 0.f, t1 = 0.f, s2 = 0.f;
#pragma unroll
                for (int nt = 0; nt < 8; nt++) {
                    int col = n0 + warpN * 64 + nt * 8 + cpair * 2;
                    float v0 = acc[mt][nt][hh * 2 + 0] + bias[col];
                    float v1 = acc[mt][nt][hh * 2 + 1] + bias[col + 1];
                    *reinterpret_cast<float2*>(&C[(size_t)row * ldc + col]) = make_float2(v0, v1);
                    float2 g2 = *reinterpret_cast<const float2*>(
                        &gum[((size_t)step * B + row) * V + col]);
                    float e0 = __expf(v0 - CSHIFT);
                    float e1 = __expf(v1 - CSHIFT);
                    s1 += e0 + e1;
                    t1 += e0 * v0 + e1 * v1;
                    s2 += __expf(v0 + g2.x - CSHIFT) + __expf(v1 + g2.y - CSHIFT);
                }
#pragma unroll
                for (int o = 1; o <= 2; o <<= 1) {
                    s1 += __shfl_xor_sync(0xffffffffu, s1, o);
                    t1 += __shfl_xor_sync(0xffffffffu, t1, o);
                    s2 += __shfl_xor_sync(0xffffffffu, s2, o);
                }
                if (cpair == 0) {
                    float* d = sp + (row * 2 + warpN) * 3;
                    d[0] = s1; d[1] = t1; d[2] = s2;
                }
            }
        __syncthreads();
        if (t < 128) {
            const float* a = sp + (t * 2 + 0) * 3;
            const float* b2 = sp + (t * 2 + 1) * 3;
            atomicAdd(&g_red[t * 4 + 0], a[0] + b2[0]);
            atomicAdd(&g_red[t * 4 + 1], a[1] + b2[1]);
            atomicAdd(&g_red[t * 4 + 2], a[2] + b2[2]);
        }
        return;
    }

#pragma unroll
    for (int mt = 0; mt < 2; mt++)
#pragma unroll
        for (int nt = 0; nt < 8; nt++)
#pragma unroll
            for (int hh = 0; hh < 2; hh++) {
                int row = warpM * 32 + mt * 16 + hh * 8 + gq;
                int col = n0 + warpN * 64 + nt * 8 + cpair * 2;
                float v0 = acc[mt][nt][hh * 2 + 0];
                float v1 = acc[mt][nt][hh * 2 + 1];
                if (bias) { v0 += bias[col]; v1 += bias[col + 1]; }
                size_t o = (size_t)row * ldc + col;
                *reinterpret_cast<float2*>(&C[o]) = make_float2(v0, v1);
                if (MODE == 2) {
                    __nv_bfloat16 h0 = __float2bfloat16(v0);
                    __nv_bfloat16 h1 = __float2bfloat16(v1);
                    Ch[o] = h0; Ch[o + 1] = h1;
                    Cl[o] = __float2bfloat16(v0 - __bfloat162float(h0));
                    Cl[o + 1] = __float2bfloat16(v1 - __bfloat162float(h1));
                }
            }
}

template <int MODE>
__global__ void __launch_bounds__(256, 2) gemm_mma(
    const __nv_bfloat16* __restrict__ Ah, const __nv_bfloat16* __restrict__ Al, int lda,
    const __nv_bfloat16* __restrict__ Bh, const __nv_bfloat16* __restrict__ Bl, int ldb,
    const float* __restrict__ bias,
    float* __restrict__ C, int ldc,
    __nv_bfloat16* __restrict__ Ch, __nv_bfloat16* __restrict__ Cl,
    int kPerSplit, const float* __restrict__ gum, int step)
{
    extern __shared__ char smem[];
    gemm_core<MODE>(Ah, Al, lda, Bh, Bl, ldb, bias, C, ldc, Ch, Cl,
                    kPerSplit, blockIdx.x, blockIdx.y, smem, gum, step);
}

// ---------------- fp32-A GEMM core (split to hi/lo at fragment load) ----------------
// Always split-K atomicAdd epilogue. A staged as fp32 (padded rows), B as bf16 hi/lo.
__device__ __forceinline__ void gemm_core32(
    const float* __restrict__ A, int lda,
    const __nv_bfloat16* __restrict__ Bh, const __nv_bfloat16* __restrict__ Bl, int ldb,
    float* __restrict__ C, int ldc,
    int kPerSplit, int bx, int by, char* smem)
{
    const u32 sb = smem_u32(smem);
    const int t = threadIdx.x;
    const int lane = t & 31, wid = t >> 5;
    const int warpM = wid & 3, warpN = wid >> 2;
    const int n0 = bx * BN;
    const int kb0 = by * kPerSplit;
    const int iters = kPerSplit / BK;

    float acc[2][8][4];
#pragma unroll
    for (int i = 0; i < 2; i++)
#pragma unroll
        for (int j = 0; j < 8; j++)
#pragma unroll
            for (int k = 0; k < 4; k++) acc[i][j][k] = 0.f;

    auto load_stage = [&](int j) {
        const int stg = j % STAGES;
        const int k0 = kb0 + j * BK;
        const u32 sbase = sb + stg * STG32;
#pragma unroll
        for (int i = 0; i < 4; i++) {
            int idx = t + i * 256;
            int row = idx >> 3, seg = idx & 7;
            const void* g = A + (size_t)row * lda + k0 + seg * 4;
            cp16(sbase + row * A32_ROWB + seg * 16, g);
        }
#pragma unroll
        for (int tile = 0; tile < 2; tile++) {
            const __nv_bfloat16* src = tile ? Bl : Bh;
#pragma unroll
            for (int i = 0; i < 2; i++) {
                int c = t + i * 256;
                int row = c >> 2, seg = c & 3;
                const void* g = src + (size_t)(n0 + row) * ldb + k0 + seg * 8;
                cp16(sbase + A32_BYTES + tile * TILE_BYTES + swz(row, seg), g);
            }
        }
        asm volatile("cp.async.commit_group;" ::: "memory");
    };

    auto compute = [&](int stg) {
        const float* As = reinterpret_cast<const float*>(smem + stg * STG32);
        const u32 bbase = sb + stg * STG32 + A32_BYTES;
#pragma unroll
        for (int ks = 0; ks < 2; ks++) {
            u32 aH[2][4], aL[2][4];
#pragma unroll
            for (int mt = 0; mt < 2; mt++) {
                int r0 = warpM * 32 + mt * 16 + (lane >> 2);
                int c0 = ks * 16 + (lane & 3) * 2;
#pragma unroll
                for (int jj = 0; jj < 4; jj++) {
                    int r = r0 + (jj & 1) * 8;
                    int c = c0 + (jj >> 1) * 8;
                    float2 f = *reinterpret_cast<const float2*>(&As[r * 36 + c]);
                    __nv_bfloat16 h0 = __float2bfloat16(f.x);
                    __nv_bfloat16 h1 = __float2bfloat16(f.y);
                    __nv_bfloat162 hp = __halves2bfloat162(h0, h1);
                    __nv_bfloat162 lp = __halves2bfloat162(
                        __float2bfloat16(f.x - __bfloat162float(h0)),
                        __float2bfloat16(f.y - __bfloat162float(h1)));
                    aH[mt][jj] = *reinterpret_cast<u32*>(&hp);
                    aL[mt][jj] = *reinterpret_cast<u32*>(&lp);
                }
            }
#pragma unroll
            for (int ntp = 0; ntp < 4; ntp++) {
                int nr = warpN * 64 + ntp * 16 + ((lane >> 4) << 3) + (lane & 7);
                int ch = ks * 2 + ((lane >> 3) & 1);
                u32 bd = bbase + swz(nr, ch);
                u32 bh[4], bl[4];
                ldsm4(bd, bh[0], bh[1], bh[2], bh[3]);
                ldsm4(bd + TILE_BYTES, bl[0], bl[1], bl[2], bl[3]);
#pragma unroll
                for (int mt = 0; mt < 2; mt++) {
                    mma16816(acc[mt][2 * ntp],     aH[mt], bh[0], bh[1]);
                    mma16816(acc[mt][2 * ntp],     aL[mt], bh[0], bh[1]);
                    mma16816(acc[mt][2 * ntp],     aH[mt], bl[0], bl[1]);
                    mma16816(acc[mt][2 * ntp + 1], aH[mt], bh[2], bh[3]);
                    mma16816(acc[mt][2 * ntp + 1], aL[mt], bh[2], bh[3]);
                    mma16816(acc[mt][2 * ntp + 1], aH[mt], bl[2], bl[3]);
                }
            }
        }
    };

    load_stage(0);
    load_stage(1);

    for (int it = 0; it < iters; it++) {
        if (it == iters - 1) asm volatile("cp.async.wait_group 0;" ::: "memory");
        else                 asm volatile("cp.async.wait_group 1;" ::: "memory");
        __syncthreads();
        int jn = it + STAGES - 1;
        if (jn < iters) load_stage(jn);
        compute(it % STAGES);
    }

    const int gq = lane >> 2, cpair = lane & 3;
#pragma unroll
    for (int mt = 0; mt < 2; mt++)
#pragma unroll
        for (int nt = 0; nt < 8; nt++)
#pragma unroll
            for (int hh = 0; hh < 2; hh++) {
                int row = warpM * 32 + mt * 16 + hh * 8 + gq;
                int col = n0 + warpN * 64 + nt * 8 + cpair * 2;
                size_t o = (size_t)row * ldc + col;
                atomicAdd(&C[o], acc[mt][nt][hh * 2 + 0]);
                atomicAdd(&C[o + 1], acc[mt][nt][hh * 2 + 1]);
            }
}

// full gates (step 0 only): 144 blocks: 48 gx (4 splits), 96 gh (8 splits)
__global__ void __launch_bounds__(256, 2) gemm_gates32(
    const float* __restrict__ e,
    const __nv_bfloat16* __restrict__ WihH, const __nv_bfloat16* __restrict__ WihL,
    float* __restrict__ gx,
    const float* __restrict__ h,
    const __nv_bfloat16* __restrict__ WhhH, const __nv_bfloat16* __restrict__ WhhL,
    float* __restrict__ gh)
{
    extern __shared__ char smem[];
    int id = blockIdx.x;
    if (id < 48) {
        gemm_core32(e, E, WihH, WihL, E, gx, TH3, 64, id % 12, id / 12, smem);
    } else {
        id -= 48;
        gemm_core32(h, H, WhhH, WhhL, H, gh, TH3, 64, id % 12, id / 12, smem);
    }
}

// gx only (steps 1..L-1): 48 blocks
__global__ void __launch_bounds__(256, 2) gemm_gx32(
    const float* __restrict__ e,
    const __nv_bfloat16* __restrict__ WihH, const __nv_bfloat16* __restrict__ WihL,
    float* __restrict__ gx)
{
    extern __shared__ char smem[];
    gemm_core32(e, E, WihH, WihL, E, gx, TH3, 64, blockIdx.x % 12, blockIdx.x / 12, smem);
}

// logits GEMM (250 CTAs, MODE 3) + next-step gh GEMM (96 CTAs) in one launch.
__global__ void __launch_bounds__(256, 2) gemm_logits_gh(
    const __nv_bfloat16* __restrict__ hH, const __nv_bfloat16* __restrict__ hL,
    const __nv_bfloat16* __restrict__ WoutH, const __nv_bfloat16* __restrict__ WoutL,
    const float* __restrict__ bout, float* __restrict__ z,
    const float* __restrict__ gum, int step,
    const float* __restrict__ h,
    const __nv_bfloat16* __restrict__ WhhH, const __nv_bfloat16* __restrict__ WhhL,
    float* __restrict__ gh)
{
    extern __shared__ char smem[];
    if (blockIdx.x < V / BN) {
        gemm_core<3>(hH, hL, H, WoutH, WoutL, H, bout, z, V, nullptr, nullptr,
                     H, blockIdx.x, 0, smem, gum, step);
    } else {
        int id = blockIdx.x - V / BN;
        gemm_core32(h, H, WhhH, WhhL, H, gh, TH3, 64, id % 12, id / 12, smem);
    }
}

// emb: A = seq output slice (fp32), split-K 100, atomicAdd into g_e
__global__ void __launch_bounds__(256, 2) gemm_emb32(
    const float* __restrict__ seq, int lda,
    const __nv_bfloat16* __restrict__ WembH, const __nv_bfloat16* __restrict__ WembL,
    float* __restrict__ eAcc)
{
    extern __shared__ char smem[];
    gemm_core32(seq, lda, WembH, WembL, V, eAcc, E, 320, blockIdx.x, blockIdx.y, smem);
}

// ---------------- fused vectorized bf16 split ----------------
struct SplitJob { const float* src; __nv_bfloat16* hi; __nv_bfloat16* lo; int n8; };
struct SplitJobs { SplitJob j[6]; };

__device__ __forceinline__ void split8(const float* __restrict__ src,
                                       __nv_bfloat16* __restrict__ hi,
                                       __nv_bfloat16* __restrict__ lo, int i) {
    const float4* s4 = reinterpret_cast<const float4*>(src);
    float4 a = s4[2 * i], b = s4[2 * i + 1];
    float v[8] = {a.x, a.y, a.z, a.w, b.x, b.y, b.z, b.w};
    __nv_bfloat162 hh[4], ll[4];
#pragma unroll
    for (int q = 0; q < 4; q++) {
        __nv_bfloat16 h0 = __float2bfloat16(v[2 * q]);
        __nv_bfloat16 h1 = __float2bfloat16(v[2 * q + 1]);
        hh[q] = __halves2bfloat162(h0, h1);
        ll[q] = __halves2bfloat162(
            __float2bfloat16(v[2 * q] - __bfloat162float(h0)),
            __float2bfloat16(v[2 * q + 1] - __bfloat162float(h1)));
    }
    reinterpret_cast<uint4*>(hi)[i] = *reinterpret_cast<uint4*>(hh);
    reinterpret_cast<uint4*>(lo)[i] = *reinterpret_cast<uint4*>(ll);
}

__global__ void k_split_all(SplitJobs js) {
    int i = blockIdx.x * 256 + threadIdx.x;
#pragma unroll
    for (int j = 0; j < 6; j++)
        if (i < js.j[j].n8) split8(js.j[j].src, js.j[j].hi, js.j[j].lo, i);
}

// ---------------- small kernels ----------------
__global__ void k_init_misc(const float* __restrict__ sos, float* __restrict__ out) {
    int idx = blockIdx.x * 256 + threadIdx.x;
    if (idx < B * V) {
        int b = idx / V, v = idx - b * V;
        out[(size_t)b * SEQ_BSTRIDE + (size_t)L * V + v] = (v == 0) ? 1.f : 0.f;
    }
    if (idx < B * E) g_e[idx] = sos[idx & (E - 1)];
    if (idx < B * TH3) { g_gx[idx] = 0.f; g_gh[idx] = 0.f; }
    if (idx < B) out[ENT_OFF + (size_t)idx * (L + 1) + L] = 0.f;
}

// GRU pointwise; zeroes consumed gate slots + g_red; reseeds g_e = bemb for emb atomics
__global__ void k_gru(const float* __restrict__ bih, const float* __restrict__ bhh,
                      const float* __restrict__ bemb) {
    int idx = blockIdx.x * 256 + threadIdx.x;
    int b = idx >> 9, j = idx & (H - 1);
    float* gx = g_gx + (size_t)b * TH3;
    float* gh = g_gh + (size_t)b * TH3;
    float r  = 1.f / (1.f + expf(-(gx[j] + bih[j] + gh[j] + bhh[j])));
    float zt = 1.f / (1.f + expf(-(gx[H + j] + bih[H + j] + gh[H + j] + bhh[H + j])));
    float nn = tanhf(gx[2 * H + j] + bih[2 * H + j] + r * (gh[2 * H + j] + bhh[2 * H + j]));
    float hn = (1.f - zt) * nn + zt * g_h[idx];
    gx[j] = 0.f; gx[H + j] = 0.f; gx[2 * H + j] = 0.f;
    gh[j] = 0.f; gh[H + j] = 0.f; gh[2 * H + j] = 0.f;
    if (idx < B * 4) g_red[idx] = 0.f;
    if (idx < B * E) g_e[idx] = bemb[idx & (E - 1)];
    g_h[idx] = hn;
    __nv_bfloat16 hb = __float2bfloat16(hn);
    g_hH[idx] = hb;
    g_hL[idx] = __float2bfloat16(hn - __bfloat162float(hb));
}

// finalize: reads per-row sums from g_red, writes seq/logits/ent.
// 4 elems/thread; grid (V/1280, B), 320 threads.
__global__ void k_final(const float* __restrict__ gum, float* __restrict__ out, int s) {
    int b = blockIdx.y;
    float S1 = g_red[b * 4 + 0];
    float T1 = g_red[b * 4 + 1];
    float S2 = g_red[b * 4 + 2];
    float lse1 = CSHIFT + logf(S1);
    float is2 = 1.f / S2;
    if (blockIdx.x == 0 && threadIdx.x == 0)
        out[ENT_OFF + (size_t)b * (L + 1) + s] = LOG2E_F * (lse1 - T1 / S1);

    int v0 = (blockIdx.x * 320 + threadIdx.x) * 4;
    float4 zv = *reinterpret_cast<const float4*>(&g_z[(size_t)b * V + v0]);
    float4 gv = *reinterpret_cast<const float4*>(&gum[((size_t)s * B + b) * V + v0]);
    float s0 = __expf(zv.x + gv.x - CSHIFT) * is2;
    float s1 = __expf(zv.y + gv.y - CSHIFT) * is2;
    float s2 = __expf(zv.z + gv.z - CSHIFT) * is2;
    float s3 = __expf(zv.w + gv.w - CSHIFT) * is2;
    *reinterpret_cast<float4*>(&out[(size_t)b * SEQ_BSTRIDE + (size_t)s * V + v0]) =
        make_float4(s0, s1, s2, s3);
    *reinterpret_cast<float4*>(&out[LOG_OFF + (size_t)b * L * V + (size_t)s * V + v0]) =
        make_float4(zv.x - lse1, zv.y - lse1, zv.z - lse1, zv.w - lse1);
}

// ---------------- launcher ----------------
extern "C" void kernel_launch(void* const* d_in, const int* in_sizes, int n_in,
                              void* d_out, int out_size) {
    const float* x       = (const float*)d_in[0];
    const float* gum     = (const float*)d_in[1];
    const float* W_agent = (const float*)d_in[2];
    const float* b_agent = (const float*)d_in[3];
    const float* Wih     = (const float*)d_in[4];
    const float* bih     = (const float*)d_in[5];
    const float* Whh     = (const float*)d_in[6];
    const float* bhh     = (const float*)d_in[7];
    const float* Wout    = (const float*)d_in[8];
    const float* bout    = (const float*)d_in[9];
    const float* Wemb    = (const float*)d_in[10];
    const float* bemb    = (const float*)d_in[11];
    const float* sos     = (const float*)d_in[12];
    float* out = (float*)d_out;

    float *ph, *pe, *pgx, *pgh, *pz;
    cudaGetSymbolAddress((void**)&ph, g_h);
    cudaGetSymbolAddress((void**)&pe, g_e);
    cudaGetSymbolAddress((void**)&pgx, g_gx);
    cudaGetSymbolAddress((void**)&pgh, g_gh);
    cudaGetSymbolAddress((void**)&pz, g_z);

    __nv_bfloat16 *WoutH, *WoutL, *WembH, *WembL, *WihH, *WihL, *WhhH, *WhhL;
    __nv_bfloat16 *WagH, *WagL, *xH, *xL, *hH, *hL;
    cudaGetSymbolAddress((void**)&WoutH, g_WoutH); cudaGetSymbolAddress((void**)&WoutL, g_WoutL);
    cudaGetSymbolAddress((void**)&WembH, g_WembH); cudaGetSymbolAddress((void**)&WembL, g_WembL);
    cudaGetSymbolAddress((void**)&WihH,  g_WihH);  cudaGetSymbolAddress((void**)&WihL,  g_WihL);
    cudaGetSymbolAddress((void**)&WhhH,  g_WhhH);  cudaGetSymbolAddress((void**)&WhhL,  g_WhhL);
    cudaGetSymbolAddress((void**)&WagH,  g_WagH);  cudaGetSymbolAddress((void**)&WagL,  g_WagL);
    cudaGetSymbolAddress((void**)&xH,    g_xH);    cudaGetSymbolAddress((void**)&xL,    g_xL);
    cudaGetSymbolAddress((void**)&hH,    g_hH);    cudaGetSymbolAddress((void**)&hL,    g_hL);

    cudaFuncSetAttribute(reinterpret_cast<const void*>(&gemm_mma<2>),
                         cudaFuncAttributeMaxDynamicSharedMemorySize, GEMM_SMEM);
    cudaFuncSetAttribute(reinterpret_cast<const void*>(&gemm_gates32),
                         cudaFuncAttributeMaxDynamicSharedMemorySize, SMEM32);
    cudaFuncSetAttribute(reinterpret_cast<const void*>(&gemm_gx32),
                         cudaFuncAttributeMaxDynamicSharedMemorySize, SMEM32);
    cudaFuncSetAttribute(reinterpret_cast<const void*>(&gemm_logits_gh),
                         cudaFuncAttributeMaxDynamicSharedMemorySize, SMEM32);
    cudaFuncSetAttribute(reinterpret_cast<const void*>(&gemm_emb32),
                         cudaFuncAttributeMaxDynamicSharedMemorySize, SMEM32);

    SplitJobs js;
    js.j[0] = { Wout,    WoutH, WoutL, V * H / 8 };
    js.j[1] = { Wemb,    WembH, WembL, E * V / 8 };
    js.j[2] = { Wih,     WihH,  WihL,  TH3 * E / 8 };
    js.j[3] = { Whh,     WhhH,  WhhL,  TH3 * H / 8 };
    js.j[4] = { W_agent, WagH,  WagL,  H * DIN / 8 };
    js.j[5] = { x,       xH,    xL,    B * DIN / 8 };
    k_split_all<<<(V * H / 8 + 255) / 256, 256>>>(js);

    // h0 = x @ W_agent^T + b_agent (emits g_h + hH/hL)
    gemm_mma<2><<<dim3(H / 128, 1), 256, GEMM_SMEM>>>(xH, xL, DIN, WagH, WagL, DIN,
                                                      b_agent, ph, H, hH, hL, DIN, nullptr, 0);
    k_init_misc<<<(B * V + 255) / 256, 256>>>(sos, out);

    for (int s = 0; s < L; s++) {
        if (s == 0) {
            // step 0: compute both gate halves (no prior logits launch to hide gh in)
            gemm_gates32<<<144, 256, SMEM32>>>(pe, WihH, WihL, pgx, ph, WhhH, WhhL, pgh);
        } else {
            // gh was already computed inside the previous step's logits launch
            gemm_gx32<<<48, 256, SMEM32>>>(pe, WihH, WihL, pgx);
        }
        k_gru<<<(B * H) / 256, 256>>>(bih, bhh, bemb);

        // logits GEMM + fused atomic softmax sums + hidden gh GEMM for next step
        gemm_logits_gh<<<V / 128 + 96, 256, SMEM32>>>(hH, hL, WoutH, WoutL, bout, pz,
                                                      gum, s, ph, WhhH, WhhL, pgh);

        k_final<<<dim3(V / 1280, B), 320>>>(gum, out, s);

        if (s < L - 1) {
            gemm_emb32<<<dim3(E / 128, 100), 256, SMEM32>>>(out + (size_t)s * V, (L + 1) * V,
                                                            WembH, WembL, pe);
        }
    }
}

// round 12
// speedup vs baseline: 1.0860x; 1.0860x over previous
#include <cuda_runtime.h>
#include <cuda_bf16.h>
#include <math.h>
#include <stdint.h>

#define B 128
#define DIN 512
#define E 256
#define H 512
#define V 32000
#define L 16
#define TH3 1536

#define LOG2E_F 1.4426950408889634f
#define CSHIFT 10.0f

typedef unsigned int u32;
typedef unsigned long long u64;

// ---------------- scratch (static device globals; no allocation) ----------------
__device__ float g_h[B * H];
__device__ float g_e[B * E];
__device__ float g_gx[B * TH3];
__device__ float g_gh[B * TH3];
__device__ float g_z[B * V];
__device__ float g_red[B * 4];            // per-row {S1, T1, S2, pad} plain sums

__device__ __nv_bfloat16 g_WoutH[V * H],  g_WoutL[V * H];
__device__ __nv_bfloat16 g_WembH[E * V],  g_WembL[E * V];
__device__ __nv_bfloat16 g_WihH[TH3 * E], g_WihL[TH3 * E];
__device__ __nv_bfloat16 g_WhhH[TH3 * H], g_WhhL[TH3 * H];
__device__ __nv_bfloat16 g_WagH[H * DIN], g_WagL[H * DIN];
__device__ __nv_bfloat16 g_xH[B * DIN],   g_xL[B * DIN];
__device__ __nv_bfloat16 g_hH[B * H],     g_hL[B * H];

#define SEQ_BSTRIDE ((size_t)(L + 1) * V)
#define LOG_OFF ((size_t)B * (L + 1) * V)
#define ENT_OFF (LOG_OFF + (size_t)B * L * V)

// ---------------- PTX helpers ----------------
__device__ __forceinline__ u32 smem_u32(const void* p) {
    u32 a;
    asm("{ .reg .u64 t; cvta.to.shared.u64 t, %1; cvt.u32.u64 %0, t; }" : "=r"(a) : "l"(p));
    return a;
}
__device__ __forceinline__ void cp16(u32 saddr, const void* g) {
    asm volatile("cp.async.cg.shared.global [%0], [%1], 16;" :: "r"(saddr), "l"(g));
}
__device__ __forceinline__ void ldsm4(u32 addr, u32& r0, u32& r1, u32& r2, u32& r3) {
    asm volatile("ldmatrix.sync.aligned.m8n8.x4.shared.b16 {%0,%1,%2,%3}, [%4];"
        : "=r"(r0), "=r"(r1), "=r"(r2), "=r"(r3) : "r"(addr));
}
__device__ __forceinline__ void mma16816(float* c, const u32* a, u32 b0, u32 b1) {
    asm volatile(
        "mma.sync.aligned.m16n8k16.row.col.f32.bf16.bf16.f32 "
        "{%0,%1,%2,%3},{%4,%5,%6,%7},{%8,%9},{%0,%1,%2,%3};"
        : "+f"(c[0]), "+f"(c[1]), "+f"(c[2]), "+f"(c[3])
        : "r"(a[0]), "r"(a[1]), "r"(a[2]), "r"(a[3]), "r"(b0), "r"(b1));
}

#define BM 128
#define BN 128
#define BK 32
#define STAGES 3
#define TILE_BYTES (BM * BK * 2)
#define STAGE_BYTES (4 * TILE_BYTES)
#define GEMM_SMEM (STAGES * STAGE_BYTES)  // 98304

// fp32-A variant smem layout
#define A32_ROWB 144                       // 36 floats per row (padded)
#define A32_BYTES (BM * A32_ROWB)          // 18432
#define STG32 (A32_BYTES + 2 * TILE_BYTES) // 34816
#define SMEM32 (STAGES * STG32)            // 104448

__device__ __forceinline__ u32 swz(int row, int seg) {
    return (u32)(row * 64 + ((seg ^ ((row >> 1) & 3)) << 4));
}

// ---------------- bf16-split HMMA GEMM core (bf16 A operands) ----------------
// MODE 2: store + bf16 split out. MODE 3: store + atomic softmax sums (logits).
template <int MODE>
__device__ __forceinline__ void gemm_core(
    const __nv_bfloat16* __restrict__ Ah, const __nv_bfloat16* __restrict__ Al, int lda,
    const __nv_bfloat16* __restrict__ Bh, const __nv_bfloat16* __restrict__ Bl, int ldb,
    const float* __restrict__ bias,
    float* __restrict__ C, int ldc,
    __nv_bfloat16* __restrict__ Ch, __nv_bfloat16* __restrict__ Cl,
    int kPerSplit, int bx, int by, char* smem,
    const float* __restrict__ gum, int step)
{
    const u32 sb = smem_u32(smem);
    const int t = threadIdx.x;
    const int lane = t & 31, wid = t >> 5;
    const int warpM = wid & 3, warpN = wid >> 2;
    const int n0 = bx * BN;
    const int kb0 = by * kPerSplit;
    const int iters = kPerSplit / BK;

    float acc[2][8][4];
#pragma unroll
    for (int i = 0; i < 2; i++)
#pragma unroll
        for (int j = 0; j < 8; j++)
#pragma unroll
            for (int k = 0; k < 4; k++) acc[i][j][k] = 0.f;

    auto load_stage = [&](int j) {
        const int stg = j % STAGES;
        const int k0 = kb0 + j * BK;
        const u32 sbase = sb + stg * STAGE_BYTES;
#pragma unroll
        for (int tile = 0; tile < 4; tile++) {
            const __nv_bfloat16* src = (tile == 0) ? Ah : (tile == 1) ? Al : (tile == 2) ? Bh : Bl;
            const int ld = (tile < 2) ? lda : ldb;
            const int r0 = (tile < 2) ? 0 : n0;
#pragma unroll
            for (int i = 0; i < 2; i++) {
                int c = t + i * 256;
                int row = c >> 2, seg = c & 3;
                const void* g = src + (size_t)(r0 + row) * ld + k0 + seg * 8;
                cp16(sbase + tile * TILE_BYTES + swz(row, seg), g);
            }
        }
        asm volatile("cp.async.commit_group;" ::: "memory");
    };

    auto compute = [&](int stg) {
        const u32 sbase = sb + stg * STAGE_BYTES;
#pragma unroll
        for (int ks = 0; ks < 2; ks++) {
            u32 aH[2][4], aL[2][4];
#pragma unroll
            for (int mt = 0; mt < 2; mt++) {
                int row = warpM * 32 + mt * 16 + (lane & 15);
                int ch = ks * 2 + (lane >> 4);
                u32 ad = sbase + swz(row, ch);
                ldsm4(ad, aH[mt][0], aH[mt][1], aH[mt][2], aH[mt][3]);
                ldsm4(ad + TILE_BYTES, aL[mt][0], aL[mt][1], aL[mt][2], aL[mt][3]);
            }
#pragma unroll
            for (int ntp = 0; ntp < 4; ntp++) {
                int nr = warpN * 64 + ntp * 16 + ((lane >> 4) << 3) + (lane & 7);
                int ch = ks * 2 + ((lane >> 3) & 1);
                u32 bd = sbase + 2 * TILE_BYTES + swz(nr, ch);
                u32 bh[4], bl[4];
                ldsm4(bd, bh[0], bh[1], bh[2], bh[3]);
                ldsm4(bd + TILE_BYTES, bl[0], bl[1], bl[2], bl[3]);
#pragma unroll
                for (int mt = 0; mt < 2; mt++) {
                    mma16816(acc[mt][2 * ntp],     aH[mt], bh[0], bh[1]);
                    mma16816(acc[mt][2 * ntp],     aL[mt], bh[0], bh[1]);
                    mma16816(acc[mt][2 * ntp],     aH[mt], bl[0], bl[1]);
                    mma16816(acc[mt][2 * ntp + 1], aH[mt], bh[2], bh[3]);
                    mma16816(acc[mt][2 * ntp + 1], aL[mt], bh[2], bh[3]);
                    mma16816(acc[mt][2 * ntp + 1], aH[mt], bl[2], bl[3]);
                }
            }
        }
    };

    load_stage(0);
    load_stage(1);

    for (int it = 0; it < iters; it++) {
        if (it == iters - 1) asm volatile("cp.async.wait_group 0;" ::: "memory");
        else                 asm volatile("cp.async.wait_group 1;" ::: "memory");
        __syncthreads();
        int jn = it + STAGES - 1;
        if (jn < iters) load_stage(jn);
        compute(it % STAGES);
    }

    const int gq = lane >> 2, cpair = lane & 3;

    if (MODE == 3) {
        // store z + per-row plain exp-sums, atomically accumulated into g_red
        __syncthreads();
        float* sp = reinterpret_cast<float*>(smem);      // [128][2][3]
#pragma unroll
        for (int mt = 0; mt < 2; mt++)
#pragma unroll
            for (int hh = 0; hh < 2; hh++) {
                const int row = warpM * 32 + mt * 16 + hh * 8 + gq;
                float s1 = 0.f, t1 = 0.f, s2 = 0.f;
#pragma unroll
                for (int nt = 0; nt < 8; nt++) {
                    int col = n0 + warpN * 64 + nt * 8 + cpair * 2;
                    float v0 = acc[mt][nt][hh * 2 + 0] + bias[col];
                    float v1 = acc[mt][nt][hh * 2 + 1] + bias[col + 1];
                    *reinterpret_cast<float2*>(&C[(size_t)row * ldc + col]) = make_float2(v0, v1);
                    float2 g2 = *reinterpret_cast<const float2*>(
                        &gum[((size_t)step * B + row) * V + col]);
                    float e0 = __expf(v0 - CSHIFT);
                    float e1 = __expf(v1 - CSHIFT);
                    s1 += e0 + e1;
                    t1 += e0 * v0 + e1 * v1;
                    s2 += __expf(v0 + g2.x - CSHIFT) + __expf(v1 + g2.y - CSHIFT);
                }
#pragma unroll
                for (int o = 1; o <= 2; o <<= 1) {
                    s1 += __shfl_xor_sync(0xffffffffu, s1, o);
                    t1 += __shfl_xor_sync(0xffffffffu, t1, o);
                    s2 += __shfl_xor_sync(0xffffffffu, s2, o);
                }
                if (cpair == 0) {
                    float* d = sp + (row * 2 + warpN) * 3;
                    d[0] = s1; d[1] = t1; d[2] = s2;
                }
            }
        __syncthreads();
        if (t < 128) {
            const float* a = sp + (t * 2 + 0) * 3;
            const float* b2 = sp + (t * 2 + 1) * 3;
            atomicAdd(&g_red[t * 4 + 0], a[0] + b2[0]);
            atomicAdd(&g_red[t * 4 + 1], a[1] + b2[1]);
            atomicAdd(&g_red[t * 4 + 2], a[2] + b2[2]);
        }
        return;
    }

#pragma unroll
    for (int mt = 0; mt < 2; mt++)
#pragma unroll
        for (int nt = 0; nt < 8; nt++)
#pragma unroll
            for (int hh = 0; hh < 2; hh++) {
                int row = warpM * 32 + mt * 16 + hh * 8 + gq;
                int col = n0 + warpN * 64 + nt * 8 + cpair * 2;
                float v0 = acc[mt][nt][hh * 2 + 0];
                float v1 = acc[mt][nt][hh * 2 + 1];
                if (bias) { v0 += bias[col]; v1 += bias[col + 1]; }
                size_t o = (size_t)row * ldc + col;
                *reinterpret_cast<float2*>(&C[o]) = make_float2(v0, v1);
                if (MODE == 2) {
                    __nv_bfloat16 h0 = __float2bfloat16(v0);
                    __nv_bfloat16 h1 = __float2bfloat16(v1);
                    Ch[o] = h0; Ch[o + 1] = h1;
                    Cl[o] = __float2bfloat16(v0 - __bfloat162float(h0));
                    Cl[o + 1] = __float2bfloat16(v1 - __bfloat162float(h1));
                }
            }
}

template <int MODE>
__global__ void __launch_bounds__(256, 2) gemm_mma(
    const __nv_bfloat16* __restrict__ Ah, const __nv_bfloat16* __restrict__ Al, int lda,
    const __nv_bfloat16* __restrict__ Bh, const __nv_bfloat16* __restrict__ Bl, int ldb,
    const float* __restrict__ bias,
    float* __restrict__ C, int ldc,
    __nv_bfloat16* __restrict__ Ch, __nv_bfloat16* __restrict__ Cl,
    int kPerSplit, const float* __restrict__ gum, int step)
{
    extern __shared__ char smem[];
    gemm_core<MODE>(Ah, Al, lda, Bh, Bl, ldb, bias, C, ldc, Ch, Cl,
                    kPerSplit, blockIdx.x, blockIdx.y, smem, gum, step);
}

// ---------------- fp32-A GEMM core (split to hi/lo at fragment load) ----------------
// Always split-K atomicAdd epilogue. A staged as fp32 (padded rows), B as bf16 hi/lo.
__device__ __forceinline__ void gemm_core32(
    const float* __restrict__ A, int lda,
    const __nv_bfloat16* __restrict__ Bh, const __nv_bfloat16* __restrict__ Bl, int ldb,
    float* __restrict__ C, int ldc,
    int kPerSplit, int bx, int by, char* smem)
{
    const u32 sb = smem_u32(smem);
    const int t = threadIdx.x;
    const int lane = t & 31, wid = t >> 5;
    const int warpM = wid & 3, warpN = wid >> 2;
    const int n0 = bx * BN;
    const int kb0 = by * kPerSplit;
    const int iters = kPerSplit / BK;

    float acc[2][8][4];
#pragma unroll
    for (int i = 0; i < 2; i++)
#pragma unroll
        for (int j = 0; j < 8; j++)
#pragma unroll
            for (int k = 0; k < 4; k++) acc[i][j][k] = 0.f;

    auto load_stage = [&](int j) {
        const int stg = j % STAGES;
        const int k0 = kb0 + j * BK;
        const u32 sbase = sb + stg * STG32;
#pragma unroll
        for (int i = 0; i < 4; i++) {
            int idx = t + i * 256;
            int row = idx >> 3, seg = idx & 7;
            const void* g = A + (size_t)row * lda + k0 + seg * 4;
            cp16(sbase + row * A32_ROWB + seg * 16, g);
        }
#pragma unroll
        for (int tile = 0; tile < 2; tile++) {
            const __nv_bfloat16* src = tile ? Bl : Bh;
#pragma unroll
            for (int i = 0; i < 2; i++) {
                int c = t + i * 256;
                int row = c >> 2, seg = c & 3;
                const void* g = src + (size_t)(n0 + row) * ldb + k0 + seg * 8;
                cp16(sbase + A32_BYTES + tile * TILE_BYTES + swz(row, seg), g);
            }
        }
        asm volatile("cp.async.commit_group;" ::: "memory");
    };

    auto compute = [&](int stg) {
        const float* As = reinterpret_cast<const float*>(smem + stg * STG32);
        const u32 bbase = sb + stg * STG32 + A32_BYTES;
#pragma unroll
        for (int ks = 0; ks < 2; ks++) {
            u32 aH[2][4], aL[2][4];
#pragma unroll
            for (int mt = 0; mt < 2; mt++) {
                int r0 = warpM * 32 + mt * 16 + (lane >> 2);
                int c0 = ks * 16 + (lane & 3) * 2;
#pragma unroll
                for (int jj = 0; jj < 4; jj++) {
                    int r = r0 + (jj & 1) * 8;
                    int c = c0 + (jj >> 1) * 8;
                    float2 f = *reinterpret_cast<const float2*>(&As[r * 36 + c]);
                    __nv_bfloat16 h0 = __float2bfloat16(f.x);
                    __nv_bfloat16 h1 = __float2bfloat16(f.y);
                    __nv_bfloat162 hp = __halves2bfloat162(h0, h1);
                    __nv_bfloat162 lp = __halves2bfloat162(
                        __float2bfloat16(f.x - __bfloat162float(h0)),
                        __float2bfloat16(f.y - __bfloat162float(h1)));
                    aH[mt][jj] = *reinterpret_cast<u32*>(&hp);
                    aL[mt][jj] = *reinterpret_cast<u32*>(&lp);
                }
            }
#pragma unroll
            for (int ntp = 0; ntp < 4; ntp++) {
                int nr = warpN * 64 + ntp * 16 + ((lane >> 4) << 3) + (lane & 7);
                int ch = ks * 2 + ((lane >> 3) & 1);
                u32 bd = bbase + swz(nr, ch);
                u32 bh[4], bl[4];
                ldsm4(bd, bh[0], bh[1], bh[2], bh[3]);
                ldsm4(bd + TILE_BYTES, bl[0], bl[1], bl[2], bl[3]);
#pragma unroll
                for (int mt = 0; mt < 2; mt++) {
                    mma16816(acc[mt][2 * ntp],     aH[mt], bh[0], bh[1]);
                    mma16816(acc[mt][2 * ntp],     aL[mt], bh[0], bh[1]);
                    mma16816(acc[mt][2 * ntp],     aH[mt], bl[0], bl[1]);
                    mma16816(acc[mt][2 * ntp + 1], aH[mt], bh[2], bh[3]);
                    mma16816(acc[mt][2 * ntp + 1], aL[mt], bh[2], bh[3]);
                    mma16816(acc[mt][2 * ntp + 1], aH[mt], bl[2], bl[3]);
                }
            }
        }
    };

    load_stage(0);
    load_stage(1);

    for (int it = 0; it < iters; it++) {
        if (it == iters - 1) asm volatile("cp.async.wait_group 0;" ::: "memory");
        else                 asm volatile("cp.async.wait_group 1;" ::: "memory");
        __syncthreads();
        int jn = it + STAGES - 1;
        if (jn < iters) load_stage(jn);
        compute(it % STAGES);
    }

    const int gq = lane >> 2, cpair = lane & 3;
#pragma unroll
    for (int mt = 0; mt < 2; mt++)
#pragma unroll
        for (int nt = 0; nt < 8; nt++)
#pragma unroll
            for (int hh = 0; hh < 2; hh++) {
                int row = warpM * 32 + mt * 16 + hh * 8 + gq;
                int col = n0 + warpN * 64 + nt * 8 + cpair * 2;
                size_t o = (size_t)row * ldc + col;
                atomicAdd(&C[o], acc[mt][nt][hh * 2 + 0]);
                atomicAdd(&C[o + 1], acc[mt][nt][hh * 2 + 1]);
            }
}

// full gates (step 0 only): 144 blocks: 48 gx (4 splits), 96 gh (8 splits)
__global__ void __launch_bounds__(256, 2) gemm_gates32(
    const float* __restrict__ e,
    const __nv_bfloat16* __restrict__ WihH, const __nv_bfloat16* __restrict__ WihL,
    float* __restrict__ gx,
    const float* __restrict__ h,
    const __nv_bfloat16* __restrict__ WhhH, const __nv_bfloat16* __restrict__ WhhL,
    float* __restrict__ gh)
{
    extern __shared__ char smem[];
    int id = blockIdx.x;
    if (id < 48) {
        gemm_core32(e, E, WihH, WihL, E, gx, TH3, 64, id % 12, id / 12, smem);
    } else {
        id -= 48;
        gemm_core32(h, H, WhhH, WhhL, H, gh, TH3, 64, id % 12, id / 12, smem);
    }
}

// gx only (steps 1..L-1): 48 blocks
__global__ void __launch_bounds__(256, 2) gemm_gx32(
    const float* __restrict__ e,
    const __nv_bfloat16* __restrict__ WihH, const __nv_bfloat16* __restrict__ WihL,
    float* __restrict__ gx)
{
    extern __shared__ char smem[];
    gemm_core32(e, E, WihH, WihL, E, gx, TH3, 64, blockIdx.x % 12, blockIdx.x / 12, smem);
}

// emb GEMM (200 CTAs) + next-step gh GEMM (96 CTAs) — 296 CTAs, one wave.
__global__ void __launch_bounds__(256, 2) gemm_emb_gh(
    const float* __restrict__ seq, int lda,
    const __nv_bfloat16* __restrict__ WembH, const __nv_bfloat16* __restrict__ WembL,
    float* __restrict__ eAcc,
    const float* __restrict__ h,
    const __nv_bfloat16* __restrict__ WhhH, const __nv_bfloat16* __restrict__ WhhL,
    float* __restrict__ gh)
{
    extern __shared__ char smem[];
    int id = blockIdx.x;
    if (id < 200) {
        gemm_core32(seq, lda, WembH, WembL, V, eAcc, E, 320, id & 1, id >> 1, smem);
    } else {
        id -= 200;
        gemm_core32(h, H, WhhH, WhhL, H, gh, TH3, 64, id % 12, id / 12, smem);
    }
}

// ---------------- fused vectorized bf16 split ----------------
struct SplitJob { const float* src; __nv_bfloat16* hi; __nv_bfloat16* lo; int n8; };
struct SplitJobs { SplitJob j[6]; };

__device__ __forceinline__ void split8(const float* __restrict__ src,
                                       __nv_bfloat16* __restrict__ hi,
                                       __nv_bfloat16* __restrict__ lo, int i) {
    const float4* s4 = reinterpret_cast<const float4*>(src);
    float4 a = s4[2 * i], b = s4[2 * i + 1];
    float v[8] = {a.x, a.y, a.z, a.w, b.x, b.y, b.z, b.w};
    __nv_bfloat162 hh[4], ll[4];
#pragma unroll
    for (int q = 0; q < 4; q++) {
        __nv_bfloat16 h0 = __float2bfloat16(v[2 * q]);
        __nv_bfloat16 h1 = __float2bfloat16(v[2 * q + 1]);
        hh[q] = __halves2bfloat162(h0, h1);
        ll[q] = __halves2bfloat162(
            __float2bfloat16(v[2 * q] - __bfloat162float(h0)),
            __float2bfloat16(v[2 * q + 1] - __bfloat162float(h1)));
    }
    reinterpret_cast<uint4*>(hi)[i] = *reinterpret_cast<uint4*>(hh);
    reinterpret_cast<uint4*>(lo)[i] = *reinterpret_cast<uint4*>(ll);
}

__global__ void k_split_all(SplitJobs js) {
    int i = blockIdx.x * 256 + threadIdx.x;
#pragma unroll
    for (int j = 0; j < 6; j++)
        if (i < js.j[j].n8) split8(js.j[j].src, js.j[j].hi, js.j[j].lo, i);
}

// ---------------- small kernels ----------------
__global__ void k_init_misc(const float* __restrict__ sos, float* __restrict__ out) {
    int idx = blockIdx.x * 256 + threadIdx.x;
    if (idx < B * V) {
        int b = idx / V, v = idx - b * V;
        out[(size_t)b * SEQ_BSTRIDE + (size_t)L * V + v] = (v == 0) ? 1.f : 0.f;
    }
    if (idx < B * E) g_e[idx] = sos[idx & (E - 1)];
    if (idx < B * TH3) { g_gx[idx] = 0.f; g_gh[idx] = 0.f; }
    if (idx < B) out[ENT_OFF + (size_t)idx * (L + 1) + L] = 0.f;
}

// GRU pointwise; zeroes consumed gate slots + g_red; reseeds g_e = bemb for emb atomics
__global__ void k_gru(const float* __restrict__ bih, const float* __restrict__ bhh,
                      const float* __restrict__ bemb) {
    int idx = blockIdx.x * 256 + threadIdx.x;
    int b = idx >> 9, j = idx & (H - 1);
    float* gx = g_gx + (size_t)b * TH3;
    float* gh = g_gh + (size_t)b * TH3;
    float r  = 1.f / (1.f + expf(-(gx[j] + bih[j] + gh[j] + bhh[j])));
    float zt = 1.f / (1.f + expf(-(gx[H + j] + bih[H + j] + gh[H + j] + bhh[H + j])));
    float nn = tanhf(gx[2 * H + j] + bih[2 * H + j] + r * (gh[2 * H + j] + bhh[2 * H + j]));
    float hn = (1.f - zt) * nn + zt * g_h[idx];
    gx[j] = 0.f; gx[H + j] = 0.f; gx[2 * H + j] = 0.f;
    gh[j] = 0.f; gh[H + j] = 0.f; gh[2 * H + j] = 0.f;
    if (idx < B * 4) g_red[idx] = 0.f;
    if (idx < B * E) g_e[idx] = bemb[idx & (E - 1)];
    g_h[idx] = hn;
    __nv_bfloat16 hb = __float2bfloat16(hn);
    g_hH[idx] = hb;
    g_hL[idx] = __float2bfloat16(hn - __bfloat162float(hb));
}

// finalize: reads per-row sums from g_red, writes seq/logits/ent.
// 4 elems/thread; grid (V/1280, B), 320 threads.
__global__ void k_final(const float* __restrict__ gum, float* __restrict__ out, int s) {
    int b = blockIdx.y;
    float S1 = g_red[b * 4 + 0];
    float T1 = g_red[b * 4 + 1];
    float S2 = g_red[b * 4 + 2];
    float lse1 = CSHIFT + logf(S1);
    float is2 = 1.f / S2;
    if (blockIdx.x == 0 && threadIdx.x == 0)
        out[ENT_OFF + (size_t)b * (L + 1) + s] = LOG2E_F * (lse1 - T1 / S1);

    int v0 = (blockIdx.x * 320 + threadIdx.x) * 4;
    float4 zv = *reinterpret_cast<const float4*>(&g_z[(size_t)b * V + v0]);
    float4 gv = *reinterpret_cast<const float4*>(&gum[((size_t)s * B + b) * V + v0]);
    float s0 = __expf(zv.x + gv.x - CSHIFT) * is2;
    float s1 = __expf(zv.y + gv.y - CSHIFT) * is2;
    float s2 = __expf(zv.z + gv.z - CSHIFT) * is2;
    float s3 = __expf(zv.w + gv.w - CSHIFT) * is2;
    *reinterpret_cast<float4*>(&out[(size_t)b * SEQ_BSTRIDE + (size_t)s * V + v0]) =
        make_float4(s0, s1, s2, s3);
    *reinterpret_cast<float4*>(&out[LOG_OFF + (size_t)b * L * V + (size_t)s * V + v0]) =
        make_float4(zv.x - lse1, zv.y - lse1, zv.z - lse1, zv.w - lse1);
}

// ---------------- launcher ----------------
extern "C" void kernel_launch(void* const* d_in, const int* in_sizes, int n_in,
                              void* d_out, int out_size) {
    const float* x       = (const float*)d_in[0];
    const float* gum     = (const float*)d_in[1];
    const float* W_agent = (const float*)d_in[2];
    const float* b_agent = (const float*)d_in[3];
    const float* Wih     = (const float*)d_in[4];
    const float* bih     = (const float*)d_in[5];
    const float* Whh     = (const float*)d_in[6];
    const float* bhh     = (const float*)d_in[7];
    const float* Wout    = (const float*)d_in[8];
    const float* bout    = (const float*)d_in[9];
    const float* Wemb    = (const float*)d_in[10];
    const float* bemb    = (const float*)d_in[11];
    const float* sos     = (const float*)d_in[12];
    float* out = (float*)d_out;

    float *ph, *pe, *pgx, *pgh, *pz;
    cudaGetSymbolAddress((void**)&ph, g_h);
    cudaGetSymbolAddress((void**)&pe, g_e);
    cudaGetSymbolAddress((void**)&pgx, g_gx);
    cudaGetSymbolAddress((void**)&pgh, g_gh);
    cudaGetSymbolAddress((void**)&pz, g_z);

    __nv_bfloat16 *WoutH, *WoutL, *WembH, *WembL, *WihH, *WihL, *WhhH, *WhhL;
    __nv_bfloat16 *WagH, *WagL, *xH, *xL, *hH, *hL;
    cudaGetSymbolAddress((void**)&WoutH, g_WoutH); cudaGetSymbolAddress((void**)&WoutL, g_WoutL);
    cudaGetSymbolAddress((void**)&WembH, g_WembH); cudaGetSymbolAddress((void**)&WembL, g_WembL);
    cudaGetSymbolAddress((void**)&WihH,  g_WihH);  cudaGetSymbolAddress((void**)&WihL,  g_WihL);
    cudaGetSymbolAddress((void**)&WhhH,  g_WhhH);  cudaGetSymbolAddress((void**)&WhhL,  g_WhhL);
    cudaGetSymbolAddress((void**)&WagH,  g_WagH);  cudaGetSymbolAddress((void**)&WagL,  g_WagL);
    cudaGetSymbolAddress((void**)&xH,    g_xH);    cudaGetSymbolAddress((void**)&xL,    g_xL);
    cudaGetSymbolAddress((void**)&hH,    g_hH);    cudaGetSymbolAddress((void**)&hL,    g_hL);

    cudaFuncSetAttribute(reinterpret_cast<const void*>(&gemm_mma<2>),
                         cudaFuncAttributeMaxDynamicSharedMemorySize, GEMM_SMEM);
    cudaFuncSetAttribute(reinterpret_cast<const void*>(&gemm_mma<3>),
                         cudaFuncAttributeMaxDynamicSharedMemorySize, GEMM_SMEM);
    cudaFuncSetAttribute(reinterpret_cast<const void*>(&gemm_gates32),
                         cudaFuncAttributeMaxDynamicSharedMemorySize, SMEM32);
    cudaFuncSetAttribute(reinterpret_cast<const void*>(&gemm_gx32),
                         cudaFuncAttributeMaxDynamicSharedMemorySize, SMEM32);
    cudaFuncSetAttribute(reinterpret_cast<const void*>(&gemm_emb_gh),
                         cudaFuncAttributeMaxDynamicSharedMemorySize, SMEM32);

    SplitJobs js;
    js.j[0] = { Wout,    WoutH, WoutL, V * H / 8 };
    js.j[1] = { Wemb,    WembH, WembL, E * V / 8 };
    js.j[2] = { Wih,     WihH,  WihL,  TH3 * E / 8 };
    js.j[3] = { Whh,     WhhH,  WhhL,  TH3 * H / 8 };
    js.j[4] = { W_agent, WagH,  WagL,  H * DIN / 8 };
    js.j[5] = { x,       xH,    xL,    B * DIN / 8 };
    k_split_all<<<(V * H / 8 + 255) / 256, 256>>>(js);

    // h0 = x @ W_agent^T + b_agent (emits g_h + hH/hL)
    gemm_mma<2><<<dim3(H / 128, 1), 256, GEMM_SMEM>>>(xH, xL, DIN, WagH, WagL, DIN,
                                                      b_agent, ph, H, hH, hL, DIN, nullptr, 0);
    k_init_misc<<<(B * V + 255) / 256, 256>>>(sos, out);

    for (int s = 0; s < L; s++) {
        if (s == 0) {
            // step 0: compute both gate halves (nothing to hide gh inside yet)
            gemm_gates32<<<144, 256, SMEM32>>>(pe, WihH, WihL, pgx, ph, WhhH, WhhL, pgh);
        } else {
            // gh was computed inside the previous step's emb launch
            gemm_gx32<<<48, 256, SMEM32>>>(pe, WihH, WihL, pgx);
        }
        k_gru<<<(B * H) / 256, 256>>>(bih, bhh, bemb);

        // logits GEMM + fused atomic softmax sums (250 CTAs, single wave)
        gemm_mma<3><<<dim3(V / 128, 1), 256, GEMM_SMEM>>>(hH, hL, H, WoutH, WoutL, H,
                                                          bout, pz, V, nullptr, nullptr,
                                                          H, gum, s);

        k_final<<<dim3(V / 1280, B), 320>>>(gum, out, s);

        if (s < L - 1) {
            // emb GEMM + hidden gh GEMM for next step (296 CTAs, one wave)
            gemm_emb_gh<<<296, 256, SMEM32>>>(out + (size_t)s * V, (L + 1) * V,
                                              WembH, WembL, pe, ph, WhhH, WhhL, pgh);
        }
    }
}